// round 11
// baseline (speedup 1.0000x reference)
#include <cuda_runtime.h>
#include <cuda_bf16.h>
#include <cuda_fp16.h>
#include <cstdint>

#define NN 50000
#define DH 128
#define GG 64
#define EPSF 1e-5f
#define EMAX 800000
#define ETOTMAX (EMAX + NN)
#define SCAN_B 256
#define SCAN_NB ((NN + SCAN_B - 1) / SCAN_B)   // 196
#define TILES ((NN + 127) / 128)               // 391
#define LDS_STRIDE 136

// ---------------- scratch ----------------
__device__ __half g_h[NN * DH];
__device__ float g_x2[NN * DH];
__device__ float g_als[NN];
__device__ float g_ald[NN];
__device__ int   g_deg[NN];
__device__ int   g_cur[NN];
__device__ int   g_off[NN + 1];
__device__ int   g_csrc[ETOTMAX];
__device__ int   g_is64;
__device__ int   g_bsum[SCAN_NB];
__device__ int   g_boff[SCAN_NB];
__device__ float g_logits[GG * DH];
__device__ __align__(16) __nv_bfloat16 g_Bh[2][16384];
__device__ __align__(16) __nv_bfloat16 g_Bl[2][16384];

__device__ __forceinline__ int idx_at(const void* p, long long i, int is64) {
    if (is64) return (int)((const long long*)p)[i];
    return ((const int*)p)[i];
}

__device__ __forceinline__ uint32_t smem_u32(const void* p) {
    uint32_t a;
    asm("{ .reg .u64 t; cvta.to.shared.u64 t, %1; cvt.u32.u64 %0, t; }"
        : "=r"(a) : "l"(p));
    return a;
}

// ---------------- dtype detection ----------------
__global__ void k_detect(const int* ei32) {
    __shared__ int bad;
    if (threadIdx.x == 0) bad = 0;
    __syncthreads();
    int t = threadIdx.x;
    int any = 0;
#pragma unroll
    for (int i = 0; i < 8; i++)
        if (ei32[2 * (t * 8 + i) + 1] != 0) any = 1;
    if (any) atomicOr(&bad, 1);
    __syncthreads();
    if (t == 0) g_is64 = !bad;
}

__global__ void k_zero() {
    for (int i = blockIdx.x * blockDim.x + threadIdx.x; i < NN;
         i += gridDim.x * blockDim.x)
        g_deg[i] = 0;
}

// ---------------- CSR build (pair-vectorized) ----------------
__global__ void k_hist(const void* ei, int E) {
    int is64 = g_is64;
    int half = E >> 1;
    int odd = E & 1;
    int tot = half + odd + NN;
    for (int i = blockIdx.x * blockDim.x + threadIdx.x; i < tot;
         i += gridDim.x * blockDim.x) {
        if (i < half) {
            int d0, d1;
            if (is64) {
                longlong2 v = ((const longlong2*)((const long long*)ei + E))[i];
                d0 = (int)v.x; d1 = (int)v.y;
            } else {
                int2 v = ((const int2*)((const int*)ei + E))[i];
                d0 = v.x; d1 = v.y;
            }
            atomicAdd(&g_deg[d0], 1);
            atomicAdd(&g_deg[d1], 1);
        } else if (odd && i == half) {
            atomicAdd(&g_deg[idx_at(ei, 2LL * E - 1, is64)], 1);
        } else {
            atomicAdd(&g_deg[i - half - odd], 1);
        }
    }
}

__global__ void __launch_bounds__(SCAN_B) k_scan_bsum() {
    __shared__ int ss[SCAN_B];
    int id = blockIdx.x * SCAN_B + threadIdx.x;
    ss[threadIdx.x] = (id < NN) ? g_deg[id] : 0;
    __syncthreads();
    for (int o = SCAN_B / 2; o > 0; o >>= 1) {
        if (threadIdx.x < o) ss[threadIdx.x] += ss[threadIdx.x + o];
        __syncthreads();
    }
    if (threadIdx.x == 0) g_bsum[blockIdx.x] = ss[0];
}

__global__ void __launch_bounds__(256) k_scan_top() {
    __shared__ int ss[256];
    int t = threadIdx.x;
    int v = (t < SCAN_NB) ? g_bsum[t] : 0;
    ss[t] = v;
    __syncthreads();
    for (int o = 1; o < 256; o <<= 1) {
        int u = (t >= o) ? ss[t - o] : 0;
        __syncthreads();
        ss[t] += u;
        __syncthreads();
    }
    if (t < SCAN_NB) g_boff[t] = ss[t] - v;
}

__global__ void __launch_bounds__(SCAN_B) k_scan_expand() {
    __shared__ int ss[SCAN_B];
    int t = threadIdx.x;
    int id = blockIdx.x * SCAN_B + t;
    int v = (id < NN) ? g_deg[id] : 0;
    ss[t] = v;
    __syncthreads();
    for (int o = 1; o < SCAN_B; o <<= 1) {
        int u = (t >= o) ? ss[t - o] : 0;
        __syncthreads();
        ss[t] += u;
        __syncthreads();
    }
    int base = g_boff[blockIdx.x];
    if (id < NN) {
        int excl = base + ss[t] - v;
        g_off[id] = excl;
        g_cur[id] = excl;
        if (id == NN - 1) g_off[NN] = base + ss[t];
    }
}

__global__ void k_scatter(const void* ei, int E) {
    int is64 = g_is64;
    int half = E >> 1;
    int odd = E & 1;
    int tot = half + odd + NN;
    for (int i = blockIdx.x * blockDim.x + threadIdx.x; i < tot;
         i += gridDim.x * blockDim.x) {
        if (i < half) {
            int s0, s1, d0, d1;
            if (is64) {
                longlong2 s = ((const longlong2*)ei)[i];
                longlong2 d = ((const longlong2*)((const long long*)ei + E))[i];
                s0 = (int)s.x; s1 = (int)s.y;
                d0 = (int)d.x; d1 = (int)d.y;
            } else {
                int2 s = ((const int2*)ei)[i];
                int2 d = ((const int2*)((const int*)ei + E))[i];
                s0 = s.x; s1 = s.y;
                d0 = d.x; d1 = d.y;
            }
            g_csrc[atomicAdd(&g_cur[d0], 1)] = s0;
            g_csrc[atomicAdd(&g_cur[d1], 1)] = s1;
        } else if (odd && i == half) {
            int s = idx_at(ei, E - 1, is64);
            int d = idx_at(ei, 2LL * E - 1, is64);
            g_csrc[atomicAdd(&g_cur[d], 1)] = s;
        } else {
            int v = i - half - odd;
            g_csrc[atomicAdd(&g_cur[v], 1)] = v;
        }
    }
}

// ---------------- W prep ----------------
__global__ void k_wprep(const float* __restrict__ W1, const float* __restrict__ W2) {
    int id = blockIdx.x * blockDim.x + threadIdx.x;
    int layer = id >> 14;
    int e = id & 16383;
    int k = e >> 7, n = e & 127;
    const float* W = layer ? W2 : W1;
    float w = W[k * 128 + n];
    __nv_bfloat16 hi = __float2bfloat16(w);
    g_Bh[layer][n * 128 + k] = hi;
    g_Bl[layer][n * 128 + k] = __float2bfloat16(w - __bfloat162float(hi));
}

// ---------------- mma.sync bf16 split GEMM (ldmatrix fragments) ----------------
__device__ __forceinline__ void mma16816(float d[4], const uint32_t a[4],
                                         const uint32_t b[2]) {
    asm volatile(
        "mma.sync.aligned.m16n8k16.row.col.f32.bf16.bf16.f32 "
        "{%0,%1,%2,%3}, {%4,%5,%6,%7}, {%8,%9}, {%0,%1,%2,%3};"
        : "+f"(d[0]), "+f"(d[1]), "+f"(d[2]), "+f"(d[3])
        : "r"(a[0]), "r"(a[1]), "r"(a[2]), "r"(a[3]), "r"(b[0]), "r"(b[1]));
}

__device__ __forceinline__ void ldsm4(uint32_t r[4], uint32_t addr) {
    asm volatile(
        "ldmatrix.sync.aligned.m8n8.x4.shared.b16 {%0,%1,%2,%3}, [%4];"
        : "=r"(r[0]), "=r"(r[1]), "=r"(r[2]), "=r"(r[3])
        : "r"(addr));
}

__device__ __forceinline__ void mma_pass(uint32_t Ab, uint32_t Bb, int lane,
                                         int wr, int wc, float acc[2][8][4]) {
    // precomputed per-lane address components
    int arow = lane & 15, ahalf = (lane >> 4) * 8;
    int brow = ((lane >> 4) * 8) + (lane & 7);  // (group>>1)*8 + rl
    int bhalf = ((lane >> 3) & 1) * 8;
#pragma unroll
    for (int ks = 0; ks < 8; ks++) {
        int k0 = ks * 16;
        uint32_t a[2][4];
        ldsm4(a[0], Ab + ((wr + arow) * LDS_STRIDE + k0 + ahalf) * 2);
        ldsm4(a[1], Ab + ((wr + 16 + arow) * LDS_STRIDE + k0 + ahalf) * 2);
        uint32_t b[8][2];
#pragma unroll
        for (int nb = 0; nb < 4; nb++) {
            uint32_t r[4];
            int n = wc + nb * 16 + brow;
            ldsm4(r, Bb + (n * LDS_STRIDE + k0 + bhalf) * 2);
            b[nb * 2][0] = r[0];
            b[nb * 2][1] = r[1];
            b[nb * 2 + 1][0] = r[2];
            b[nb * 2 + 1][1] = r[3];
        }
#pragma unroll
        for (int mi = 0; mi < 2; mi++)
#pragma unroll
            for (int ni = 0; ni < 8; ni++) mma16816(acc[mi][ni], a[mi], b[ni]);
    }
}

#define SM_BH  (128 * LDS_STRIDE)
#define SM_BL  (2 * 128 * LDS_STRIDE)
#define SM_FLT (3 * 128 * LDS_STRIDE)
#define HMMA_SMEM (SM_FLT * 2 + (256 + 256 + 128 + 128) * 4)

__global__ void __launch_bounds__(256, 2)
k_hmma(const float* __restrict__ Xext, int layer,
       const float* __restrict__ asrc, const float* __restrict__ adst) {
    extern __shared__ __align__(16) char sm[];
    __nv_bfloat16* As = (__nv_bfloat16*)sm;
    __nv_bfloat16* Bh = As + SM_BH;
    __nv_bfloat16* Bl = As + SM_BL;
    float* sps = (float*)(sm + SM_FLT * 2);
    float* spd = sps + 256;
    float* s_as = spd + 256;
    float* s_ad = s_as + 128;

    const float* X = layer ? g_x2 : Xext;
    int tid = threadIdx.x;
    int wid = tid >> 5, lane = tid & 31;
    int gid = lane >> 2, tig = lane & 3;
    int wr = (wid & 3) * 32;
    int wc = (wid >> 2) * 64;
    int rowBase = blockIdx.x * 128;
    uint32_t As32 = smem_u32(As);
    uint32_t Bh32 = smem_u32(Bh);
    uint32_t Bl32 = smem_u32(Bl);

    {
        const int4* gh = (const int4*)g_Bh[layer];
        const int4* gl = (const int4*)g_Bl[layer];
#pragma unroll
        for (int i = tid; i < 2048; i += 256) {
            int r = i >> 4, c = i & 15;
            *(int4*)((char*)Bh + r * (LDS_STRIDE * 2) + c * 16) = gh[i];
            *(int4*)((char*)Bl + r * (LDS_STRIDE * 2) + c * 16) = gl[i];
        }
    }
    if (tid < 128) {
        s_as[tid] = asrc[tid];
        s_ad[tid] = adst[tid];
    }
#pragma unroll
    for (int i = 0; i < 32; i++) {
        int f = tid + i * 256;
        int r = f >> 6, kp = f & 63;
        int row = rowBase + r;
        float2 v = make_float2(0.f, 0.f);
        if (row < NN) v = *(const float2*)&X[row * DH + kp * 2];
        *(__nv_bfloat162*)&As[r * LDS_STRIDE + kp * 2] =
            __halves2bfloat162(__float2bfloat16(v.x), __float2bfloat16(v.y));
    }
    __syncthreads();

    float acc[2][8][4];
#pragma unroll
    for (int mi = 0; mi < 2; mi++)
#pragma unroll
        for (int ni = 0; ni < 8; ni++)
#pragma unroll
            for (int q = 0; q < 4; q++) acc[mi][ni][q] = 0.f;

    mma_pass(As32, Bh32, lane, wr, wc, acc);     // hi * hi
    mma_pass(As32, Bl32, lane, wr, wc, acc);     // hi * lo
    __syncthreads();
#pragma unroll
    for (int i = 0; i < 32; i++) {
        int f = tid + i * 256;
        int r = f >> 6, kp = f & 63;
        int row = rowBase + r;
        float2 v = make_float2(0.f, 0.f);
        if (row < NN) v = *(const float2*)&X[row * DH + kp * 2];
        float lx = v.x - __bfloat162float(__float2bfloat16(v.x));
        float ly = v.y - __bfloat162float(__float2bfloat16(v.y));
        *(__nv_bfloat162*)&As[r * LDS_STRIDE + kp * 2] =
            __halves2bfloat162(__float2bfloat16(lx), __float2bfloat16(ly));
    }
    __syncthreads();
    mma_pass(As32, Bh32, lane, wr, wc, acc);     // lo * hi

    float ps[4] = {0.f, 0.f, 0.f, 0.f};
    float pd[4] = {0.f, 0.f, 0.f, 0.f};
#pragma unroll
    for (int mi = 0; mi < 2; mi++) {
#pragma unroll
        for (int ni = 0; ni < 8; ni++) {
            int col = wc + ni * 8 + tig * 2;
            float a0 = s_as[col], a1 = s_as[col + 1];
            float d0 = s_ad[col], d1 = s_ad[col + 1];
            float* v = acc[mi][ni];
            ps[mi * 2 + 0] += v[0] * a0 + v[1] * a1;
            pd[mi * 2 + 0] += v[0] * d0 + v[1] * d1;
            ps[mi * 2 + 1] += v[2] * a0 + v[3] * a1;
            pd[mi * 2 + 1] += v[2] * d0 + v[3] * d1;
            int r0 = rowBase + wr + mi * 16 + gid;
            if (r0 < NN)
                *(__half2*)&g_h[r0 * DH + col] = __floats2half2_rn(v[0], v[1]);
            if (r0 + 8 < NN)
                *(__half2*)&g_h[(r0 + 8) * DH + col] = __floats2half2_rn(v[2], v[3]);
        }
    }
#pragma unroll
    for (int j = 0; j < 4; j++) {
#pragma unroll
        for (int o = 1; o <= 2; o <<= 1) {
            ps[j] += __shfl_xor_sync(0xffffffffu, ps[j], o);
            pd[j] += __shfl_xor_sync(0xffffffffu, pd[j], o);
        }
    }
    if (tig == 0) {
        int ch = wid >> 2;
#pragma unroll
        for (int j = 0; j < 4; j++) {
            int rloc = wr + (j >> 1) * 16 + (j & 1) * 8 + gid;
            sps[rloc * 2 + ch] = ps[j];
            spd[rloc * 2 + ch] = pd[j];
        }
    }
    __syncthreads();
    if (tid < 128 && rowBase + tid < NN) {
        g_als[rowBase + tid] = sps[tid * 2] + sps[tid * 2 + 1];
        g_ald[rowBase + tid] = spd[tid * 2] + spd[tid * 2 + 1];
    }
}

// ---------------- warp-per-node aggregation (fp16 h rows) ----------------
template <int MODE>
__global__ void __launch_bounds__(256) k_agg(const float* __restrict__ bias,
                                             const float* __restrict__ lng,
                                             const float* __restrict__ lnb) {
    int w = (blockIdx.x * blockDim.x + threadIdx.x) >> 5;
    int lane = threadIdx.x & 31;
    if (w >= NN) return;
    int js = g_off[w], je = g_off[w + 1];
    float aldv = g_ald[w];
    float ax = 0.f, ay = 0.f, az = 0.f, aw = 0.f, z = 0.f;
    const uint2* hrow = (const uint2*)g_h;

    for (int base = js; base < je; base += 32) {
        int cnt = min(32, je - base);
        int idx = w;
        float ef = 0.f;
        if (lane < cnt) {
            idx = g_csrc[base + lane];
            float a = g_als[idx] + aldv;
            a = a > 0.f ? a : 0.2f * a;
            ef = __expf(a);
        }
        int j = 0;
        for (; j + 4 <= cnt; j += 4) {
            int s0 = __shfl_sync(0xffffffffu, idx, j);
            int s1 = __shfl_sync(0xffffffffu, idx, j + 1);
            int s2 = __shfl_sync(0xffffffffu, idx, j + 2);
            int s3 = __shfl_sync(0xffffffffu, idx, j + 3);
            float e0 = __shfl_sync(0xffffffffu, ef, j);
            float e1 = __shfl_sync(0xffffffffu, ef, j + 1);
            float e2 = __shfl_sync(0xffffffffu, ef, j + 2);
            float e3 = __shfl_sync(0xffffffffu, ef, j + 3);
            uint2 u0 = hrow[s0 * 32 + lane];
            uint2 u1 = hrow[s1 * 32 + lane];
            uint2 u2 = hrow[s2 * 32 + lane];
            uint2 u3 = hrow[s3 * 32 + lane];
            float2 a0 = __half22float2(*(__half2*)&u0.x), b0 = __half22float2(*(__half2*)&u0.y);
            float2 a1 = __half22float2(*(__half2*)&u1.x), b1 = __half22float2(*(__half2*)&u1.y);
            float2 a2 = __half22float2(*(__half2*)&u2.x), b2 = __half22float2(*(__half2*)&u2.y);
            float2 a3 = __half22float2(*(__half2*)&u3.x), b3 = __half22float2(*(__half2*)&u3.y);
            ax += e0 * a0.x + e1 * a1.x + e2 * a2.x + e3 * a3.x;
            ay += e0 * a0.y + e1 * a1.y + e2 * a2.y + e3 * a3.y;
            az += e0 * b0.x + e1 * b1.x + e2 * b2.x + e3 * b3.x;
            aw += e0 * b0.y + e1 * b1.y + e2 * b2.y + e3 * b3.y;
            z += e0 + e1 + e2 + e3;
        }
        for (; j < cnt; j++) {
            int s = __shfl_sync(0xffffffffu, idx, j);
            float e = __shfl_sync(0xffffffffu, ef, j);
            uint2 u = hrow[s * 32 + lane];
            float2 f0 = __half22float2(*(__half2*)&u.x);
            float2 f1 = __half22float2(*(__half2*)&u.y);
            ax += e * f0.x;
            ay += e * f0.y;
            az += e * f1.x;
            aw += e * f1.y;
            z += e;
        }
    }
    float inv = 1.f / z;
    float4 b4 = *(const float4*)&bias[lane * 4];
    float c0 = ax * inv + b4.x;
    float c1 = ay * inv + b4.y;
    float c2 = az * inv + b4.z;
    float c3 = aw * inv + b4.w;
    if (MODE == 1) {
        c0 = fmaxf(c0, 0.f); c1 = fmaxf(c1, 0.f);
        c2 = fmaxf(c2, 0.f); c3 = fmaxf(c3, 0.f);
    }
    float tot = c0 + c1 + c2 + c3;
#pragma unroll
    for (int o = 16; o > 0; o >>= 1) tot += __shfl_xor_sync(0xffffffffu, tot, o);
    float mu = tot * (1.f / DH);
    float d0 = c0 - mu, d1 = c1 - mu, d2 = c2 - mu, d3 = c3 - mu;
    float ssq = d0 * d0 + d1 * d1 + d2 * d2 + d3 * d3;
#pragma unroll
    for (int o = 16; o > 0; o >>= 1) ssq += __shfl_xor_sync(0xffffffffu, ssq, o);
    float var = ssq * (1.f / DH);
    float sc = rsqrtf(var + EPSF);
    float4 g4 = *(const float4*)&lng[lane * 4];
    float4 bb = *(const float4*)&lnb[lane * 4];
    float o0 = d0 * sc * g4.x + bb.x;
    float o1 = d1 * sc * g4.y + bb.y;
    float o2 = d2 * sc * g4.z + bb.z;
    float o3 = d3 * sc * g4.w + bb.w;
    if (MODE == 2) {
        o0 = fmaxf(o0, 0.f); o1 = fmaxf(o1, 0.f);
        o2 = fmaxf(o2, 0.f); o3 = fmaxf(o3, 0.f);
    }
    *(float4*)&g_x2[w * DH + lane * 4] = make_float4(o0, o1, o2, o3);
}

// ---------------- fused bounds + pool + fc ----------------
__global__ void __launch_bounds__(512) k_poolfc(const void* batch,
                                                const float* __restrict__ fcW,
                                                const float* __restrict__ fcb) {
    __shared__ float part[4][DH];
    __shared__ float pr[DH];
    __shared__ int sbound[2];
    int g = blockIdx.x;
    int t = threadIdx.x;
    if (t < 2) {
        int is64 = g_is64;
        int target = g + t;
        int lo = 0, hi = NN;
        while (lo < hi) {
            int m = (lo + hi) >> 1;
            if (idx_at(batch, m, is64) < target) lo = m + 1;
            else hi = m;
        }
        sbound[t] = lo;
    }
    __syncthreads();
    int s = sbound[0], e = sbound[1];
    int c = t & 127;
    int q = t >> 7;
    int cnt = e - s;
    int chunk = (cnt + 3) >> 2;
    int rs = s + q * chunk;
    int re = min(rs + chunk, e);
    float sum = 0.f;
    for (int r = rs; r < re; r++) sum += g_x2[r * DH + c];
    part[q][c] = sum;
    __syncthreads();
    if (q == 0) {
        float tot2 = part[0][c] + part[1][c] + part[2][c] + part[3][c];
        pr[c] = tot2 / (float)max(cnt, 1);
    }
    __syncthreads();
    if (t < 128) {
        float acc = fcb[t];
#pragma unroll 4
        for (int k = 0; k < DH; k++) acc += pr[k] * fcW[k * DH + t];
        g_logits[g * DH + t] = acc;
    }
}

__global__ void k_bn(const float* __restrict__ bng, const float* __restrict__ bnb,
                     float* __restrict__ out) {
    int o = threadIdx.x;
    float mu = 0.f;
    for (int g = 0; g < GG; g++) mu += g_logits[g * DH + o];
    mu *= (1.f / GG);
    float var = 0.f;
    for (int g = 0; g < GG; g++) {
        float d = g_logits[g * DH + o] - mu;
        var += d * d;
    }
    var *= (1.f / GG);
    float sc = rsqrtf(var + EPSF);
    float gg = bng[o], bb = bnb[o];
    for (int g = 0; g < GG; g++)
        out[g * DH + o] = (g_logits[g * DH + o] - mu) * sc * gg + bb;
}

// ---------------- launch ----------------
extern "C" void kernel_launch(void* const* d_in, const int* in_sizes, int n_in,
                              void* d_out, int out_size) {
    const float* x    = (const float*)d_in[0];
    const void*  ei   = d_in[1];
    const void*  bat  = d_in[2];
    const float* W1   = (const float*)d_in[3];
    const float* as1  = (const float*)d_in[4];
    const float* ad1  = (const float*)d_in[5];
    const float* b1   = (const float*)d_in[6];
    const float* W2   = (const float*)d_in[7];
    const float* as2  = (const float*)d_in[8];
    const float* ad2  = (const float*)d_in[9];
    const float* b2   = (const float*)d_in[10];
    const float* ln1g = (const float*)d_in[11];
    const float* ln1b = (const float*)d_in[12];
    const float* ln2g = (const float*)d_in[13];
    const float* ln2b = (const float*)d_in[14];
    const float* fcW  = (const float*)d_in[15];
    const float* fcb  = (const float*)d_in[16];
    const float* bng  = (const float*)d_in[17];
    const float* bnb  = (const float*)d_in[18];
    float* out = (float*)d_out;
    int E = in_sizes[1] / 2;

    cudaFuncSetAttribute(k_hmma, cudaFuncAttributeMaxDynamicSharedMemorySize, HMMA_SMEM);

    // hmma1 stays the 4th launch for profiling continuity
    k_zero<<<98, 512>>>();
    k_wprep<<<128, 256>>>(W1, W2);
    k_detect<<<1, 256>>>((const int*)ei);
    k_hmma<<<TILES, 256, HMMA_SMEM>>>(x, 0, as1, ad1);

    k_hist<<<1024, 256>>>(ei, E);
    k_scan_bsum<<<SCAN_NB, SCAN_B>>>();
    k_scan_top<<<1, 256>>>();
    k_scan_expand<<<SCAN_NB, SCAN_B>>>();
    k_scatter<<<1024, 256>>>(ei, E);

    k_agg<1><<<NN / 8, 256>>>(b1, ln1g, ln1b);

    k_hmma<<<TILES, 256, HMMA_SMEM>>>(nullptr, 1, as2, ad2);
    k_agg<2><<<NN / 8, 256>>>(b2, ln2g, ln2b);

    k_poolfc<<<GG, 512>>>(bat, fcW, fcb);
    k_bn<<<1, 128>>>(bng, bnb, out);
}

// round 16
// speedup vs baseline: 1.0784x; 1.0784x over previous
#include <cuda_runtime.h>
#include <cuda_fp16.h>
#include <cstdint>

#define NN 50000
#define DH 128
#define GG 64
#define EPSF 1e-5f
#define EMAX 800000
#define ETOTMAX (EMAX + NN)
#define SCAN_B 256
#define SCAN_NB ((NN + SCAN_B - 1) / SCAN_B)   // 196
#define TILES ((NN + 127) / 128)               // 391
#define LDS_STRIDE 136

// ---------------- scratch ----------------
__device__ __half g_h[NN * DH];
__device__ float g_x2[NN * DH];
__device__ float g_als[NN];
__device__ float g_ald[NN];
__device__ int   g_deg[NN];
__device__ int   g_cur[NN];
__device__ int   g_off[NN + 1];
__device__ int   g_csrc[ETOTMAX];
__device__ int   g_is64;
__device__ int   g_bsum[SCAN_NB];
__device__ int   g_boff[SCAN_NB];
__device__ float g_logits[GG * DH];
// W^T fp16: [layer][n*128+k]
__device__ __align__(16) __half g_Wh[2][16384];

__device__ __forceinline__ int idx_at(const void* p, long long i, int is64) {
    if (is64) return (int)((const long long*)p)[i];
    return ((const int*)p)[i];
}

// ---------------- dtype detection ----------------
__global__ void k_detect(const int* ei32) {
    __shared__ int bad;
    if (threadIdx.x == 0) bad = 0;
    __syncthreads();
    int t = threadIdx.x;
    int any = 0;
#pragma unroll
    for (int i = 0; i < 8; i++)
        if (ei32[2 * (t * 8 + i) + 1] != 0) any = 1;
    if (any) atomicOr(&bad, 1);
    __syncthreads();
    if (t == 0) g_is64 = !bad;
}

__global__ void k_zero() {
    for (int i = blockIdx.x * blockDim.x + threadIdx.x; i < NN;
         i += gridDim.x * blockDim.x)
        g_deg[i] = 0;
}

// ---------------- CSR build (pair-vectorized) ----------------
__global__ void k_hist(const void* ei, int E) {
    int is64 = g_is64;
    int half = E >> 1;
    int odd = E & 1;
    int tot = half + odd + NN;
    for (int i = blockIdx.x * blockDim.x + threadIdx.x; i < tot;
         i += gridDim.x * blockDim.x) {
        if (i < half) {
            int d0, d1;
            if (is64) {
                longlong2 v = ((const longlong2*)((const long long*)ei + E))[i];
                d0 = (int)v.x; d1 = (int)v.y;
            } else {
                int2 v = ((const int2*)((const int*)ei + E))[i];
                d0 = v.x; d1 = v.y;
            }
            atomicAdd(&g_deg[d0], 1);
            atomicAdd(&g_deg[d1], 1);
        } else if (odd && i == half) {
            atomicAdd(&g_deg[idx_at(ei, 2LL * E - 1, is64)], 1);
        } else {
            atomicAdd(&g_deg[i - half - odd], 1);
        }
    }
}

__global__ void __launch_bounds__(SCAN_B) k_scan_bsum() {
    __shared__ int ss[SCAN_B];
    int id = blockIdx.x * SCAN_B + threadIdx.x;
    ss[threadIdx.x] = (id < NN) ? g_deg[id] : 0;
    __syncthreads();
    for (int o = SCAN_B / 2; o > 0; o >>= 1) {
        if (threadIdx.x < o) ss[threadIdx.x] += ss[threadIdx.x + o];
        __syncthreads();
    }
    if (threadIdx.x == 0) g_bsum[blockIdx.x] = ss[0];
}

__global__ void __launch_bounds__(256) k_scan_top() {
    __shared__ int ss[256];
    int t = threadIdx.x;
    int v = (t < SCAN_NB) ? g_bsum[t] : 0;
    ss[t] = v;
    __syncthreads();
    for (int o = 1; o < 256; o <<= 1) {
        int u = (t >= o) ? ss[t - o] : 0;
        __syncthreads();
        ss[t] += u;
        __syncthreads();
    }
    if (t < SCAN_NB) g_boff[t] = ss[t] - v;
}

__global__ void __launch_bounds__(SCAN_B) k_scan_expand() {
    __shared__ int ss[SCAN_B];
    int t = threadIdx.x;
    int id = blockIdx.x * SCAN_B + t;
    int v = (id < NN) ? g_deg[id] : 0;
    ss[t] = v;
    __syncthreads();
    for (int o = 1; o < SCAN_B; o <<= 1) {
        int u = (t >= o) ? ss[t - o] : 0;
        __syncthreads();
        ss[t] += u;
        __syncthreads();
    }
    int base = g_boff[blockIdx.x];
    if (id < NN) {
        int excl = base + ss[t] - v;
        g_off[id] = excl;
        g_cur[id] = excl;
        if (id == NN - 1) g_off[NN] = base + ss[t];
    }
}

__global__ void k_scatter(const void* ei, int E) {
    int is64 = g_is64;
    int half = E >> 1;
    int odd = E & 1;
    int tot = half + odd + NN;
    for (int i = blockIdx.x * blockDim.x + threadIdx.x; i < tot;
         i += gridDim.x * blockDim.x) {
        if (i < half) {
            int s0, s1, d0, d1;
            if (is64) {
                longlong2 s = ((const longlong2*)ei)[i];
                longlong2 d = ((const longlong2*)((const long long*)ei + E))[i];
                s0 = (int)s.x; s1 = (int)s.y;
                d0 = (int)d.x; d1 = (int)d.y;
            } else {
                int2 s = ((const int2*)ei)[i];
                int2 d = ((const int2*)((const int*)ei + E))[i];
                s0 = s.x; s1 = s.y;
                d0 = d.x; d1 = d.y;
            }
            g_csrc[atomicAdd(&g_cur[d0], 1)] = s0;
            g_csrc[atomicAdd(&g_cur[d1], 1)] = s1;
        } else if (odd && i == half) {
            int s = idx_at(ei, E - 1, is64);
            int d = idx_at(ei, 2LL * E - 1, is64);
            g_csrc[atomicAdd(&g_cur[d], 1)] = s;
        } else {
            int v = i - half - odd;
            g_csrc[atomicAdd(&g_cur[v], 1)] = v;
        }
    }
}

// ---------------- W prep: fp32 W[k][n] -> fp16 W^T[n][k] ----------------
__global__ void k_wprep(const float* __restrict__ W1, const float* __restrict__ W2) {
    int id = blockIdx.x * blockDim.x + threadIdx.x;
    int layer = id >> 14;
    int e = id & 16383;
    int k = e >> 7, n = e & 127;
    const float* W = layer ? W2 : W1;
    g_Wh[layer][n * 128 + k] = __float2half_rn(W[k * 128 + n]);
}

// ---------------- mma.sync fp16 2-pass split GEMM + fused attention logits ----------------
__device__ __forceinline__ void mma16816(float d[4], const uint32_t a[4],
                                         const uint32_t b[2]) {
    asm volatile(
        "mma.sync.aligned.m16n8k16.row.col.f32.f16.f16.f32 "
        "{%0,%1,%2,%3}, {%4,%5,%6,%7}, {%8,%9}, {%0,%1,%2,%3};"
        : "+f"(d[0]), "+f"(d[1]), "+f"(d[2]), "+f"(d[3])
        : "r"(a[0]), "r"(a[1]), "r"(a[2]), "r"(a[3]), "r"(b[0]), "r"(b[1]));
}

__device__ __forceinline__ void mma_pass(const __half* __restrict__ A,
                                         const __half* __restrict__ B,
                                         int wr, int wc, int gid, int tig,
                                         float acc[2][8][4]) {
#pragma unroll
    for (int ks = 0; ks < 8; ks++) {
        int k0 = ks * 16;
        uint32_t a[2][4];
#pragma unroll
        for (int mi = 0; mi < 2; mi++) {
            const __half* p = A + (wr + mi * 16 + gid) * LDS_STRIDE + k0 + tig * 2;
            a[mi][0] = *(const uint32_t*)(p);
            a[mi][1] = *(const uint32_t*)(p + 8 * LDS_STRIDE);
            a[mi][2] = *(const uint32_t*)(p + 8);
            a[mi][3] = *(const uint32_t*)(p + 8 * LDS_STRIDE + 8);
        }
        uint32_t b[8][2];
#pragma unroll
        for (int ni = 0; ni < 8; ni++) {
            const __half* p = B + (wc + ni * 8 + gid) * LDS_STRIDE + k0 + tig * 2;
            b[ni][0] = *(const uint32_t*)(p);
            b[ni][1] = *(const uint32_t*)(p + 8);
        }
#pragma unroll
        for (int mi = 0; mi < 2; mi++)
#pragma unroll
            for (int ni = 0; ni < 8; ni++) mma16816(acc[mi][ni], a[mi], b[ni]);
    }
}

// smem: Ah[128][136], Al[128][136], Bh[128][136] fp16, then reduce arrays
#define SM_AL  (128 * LDS_STRIDE)
#define SM_BH  (2 * 128 * LDS_STRIDE)
#define SM_FLT (3 * 128 * LDS_STRIDE)          // half elems before float region
#define HMMA_SMEM (SM_FLT * 2 + (256 + 256 + 128 + 128) * 4)

__global__ void __launch_bounds__(256, 2)
k_hmma(const float* __restrict__ Xext, int layer,
       const float* __restrict__ asrc, const float* __restrict__ adst) {
    extern __shared__ __align__(16) char sm[];
    __half* Ah = (__half*)sm;
    __half* Al = Ah + SM_AL;
    __half* Bh = Ah + SM_BH;
    float* sps = (float*)(sm + SM_FLT * 2);     // [128][2]
    float* spd = sps + 256;
    float* s_as = spd + 256;
    float* s_ad = s_as + 128;

    const float* X = layer ? g_x2 : Xext;
    int tid = threadIdx.x;
    int wid = tid >> 5, lane = tid & 31;
    int gid = lane >> 2, tig = lane & 3;
    int wr = (wid & 3) * 32;
    int wc = (wid >> 2) * 64;
    int rowBase = blockIdx.x * 128;

    // copy fp16 W^T tile (32 KB = 2048 int4, 16 int4 per 256-B row)
    {
        const int4* gh = (const int4*)g_Wh[layer];
#pragma unroll
        for (int i = tid; i < 2048; i += 256) {
            int r = i >> 4, c = i & 15;
            *(int4*)((char*)Bh + r * (LDS_STRIDE * 2) + c * 16) = gh[i];
        }
    }
    if (tid < 128) {
        s_as[tid] = asrc[tid];
        s_ad[tid] = adst[tid];
    }
    // single X read: produce hi + lo fp16 tiles
#pragma unroll
    for (int i = 0; i < 32; i++) {
        int f = tid + i * 256;
        int r = f >> 6, kp = f & 63;
        int row = rowBase + r;
        float2 v = make_float2(0.f, 0.f);
        if (row < NN) v = *(const float2*)&X[row * DH + kp * 2];
        __half hx = __float2half_rn(v.x);
        __half hy = __float2half_rn(v.y);
        __half lx = __float2half_rn(v.x - __half2float(hx));
        __half ly = __float2half_rn(v.y - __half2float(hy));
        *(__half2*)&Ah[r * LDS_STRIDE + kp * 2] = __halves2half2(hx, hy);
        *(__half2*)&Al[r * LDS_STRIDE + kp * 2] = __halves2half2(lx, ly);
    }
    __syncthreads();

    float acc[2][8][4];
#pragma unroll
    for (int mi = 0; mi < 2; mi++)
#pragma unroll
        for (int ni = 0; ni < 8; ni++)
#pragma unroll
            for (int q = 0; q < 4; q++) acc[mi][ni][q] = 0.f;

    mma_pass(Ah, Bh, wr, wc, gid, tig, acc);    // hi * W
    mma_pass(Al, Bh, wr, wc, gid, tig, acc);    // lo * W

    // epilogue: store fp16 h, compute als/ald partials
    float ps[4] = {0.f, 0.f, 0.f, 0.f};
    float pd[4] = {0.f, 0.f, 0.f, 0.f};
#pragma unroll
    for (int mi = 0; mi < 2; mi++) {
#pragma unroll
        for (int ni = 0; ni < 8; ni++) {
            int col = wc + ni * 8 + tig * 2;
            float a0 = s_as[col], a1 = s_as[col + 1];
            float d0 = s_ad[col], d1 = s_ad[col + 1];
            float* v = acc[mi][ni];
            ps[mi * 2 + 0] += v[0] * a0 + v[1] * a1;
            pd[mi * 2 + 0] += v[0] * d0 + v[1] * d1;
            ps[mi * 2 + 1] += v[2] * a0 + v[3] * a1;
            pd[mi * 2 + 1] += v[2] * d0 + v[3] * d1;
            int r0 = rowBase + wr + mi * 16 + gid;
            if (r0 < NN)
                *(__half2*)&g_h[r0 * DH + col] = __floats2half2_rn(v[0], v[1]);
            if (r0 + 8 < NN)
                *(__half2*)&g_h[(r0 + 8) * DH + col] = __floats2half2_rn(v[2], v[3]);
        }
    }
#pragma unroll
    for (int j = 0; j < 4; j++) {
#pragma unroll
        for (int o = 1; o <= 2; o <<= 1) {
            ps[j] += __shfl_xor_sync(0xffffffffu, ps[j], o);
            pd[j] += __shfl_xor_sync(0xffffffffu, pd[j], o);
        }
    }
    if (tig == 0) {
        int ch = wid >> 2;
#pragma unroll
        for (int j = 0; j < 4; j++) {
            int rloc = wr + (j >> 1) * 16 + (j & 1) * 8 + gid;
            sps[rloc * 2 + ch] = ps[j];
            spd[rloc * 2 + ch] = pd[j];
        }
    }
    __syncthreads();
    if (tid < 128 && rowBase + tid < NN) {
        g_als[rowBase + tid] = sps[tid * 2] + sps[tid * 2 + 1];
        g_ald[rowBase + tid] = spd[tid * 2] + spd[tid * 2 + 1];
    }
}

// ---------------- warp-per-node aggregation (fp16 h rows) ----------------
template <int MODE>
__global__ void __launch_bounds__(256) k_agg(const float* __restrict__ bias,
                                             const float* __restrict__ lng,
                                             const float* __restrict__ lnb) {
    int w = (blockIdx.x * blockDim.x + threadIdx.x) >> 5;
    int lane = threadIdx.x & 31;
    if (w >= NN) return;
    int js = g_off[w], je = g_off[w + 1];
    float aldv = g_ald[w];
    float ax = 0.f, ay = 0.f, az = 0.f, aw = 0.f, z = 0.f;
    const uint2* hrow = (const uint2*)g_h;

    for (int base = js; base < je; base += 32) {
        int cnt = min(32, je - base);
        int idx = w;
        float ef = 0.f;
        if (lane < cnt) {
            idx = g_csrc[base + lane];
            float a = g_als[idx] + aldv;
            a = a > 0.f ? a : 0.2f * a;
            ef = __expf(a);
        }
        int j = 0;
        for (; j + 4 <= cnt; j += 4) {
            int s0 = __shfl_sync(0xffffffffu, idx, j);
            int s1 = __shfl_sync(0xffffffffu, idx, j + 1);
            int s2 = __shfl_sync(0xffffffffu, idx, j + 2);
            int s3 = __shfl_sync(0xffffffffu, idx, j + 3);
            float e0 = __shfl_sync(0xffffffffu, ef, j);
            float e1 = __shfl_sync(0xffffffffu, ef, j + 1);
            float e2 = __shfl_sync(0xffffffffu, ef, j + 2);
            float e3 = __shfl_sync(0xffffffffu, ef, j + 3);
            uint2 u0 = hrow[s0 * 32 + lane];
            uint2 u1 = hrow[s1 * 32 + lane];
            uint2 u2 = hrow[s2 * 32 + lane];
            uint2 u3 = hrow[s3 * 32 + lane];
            float2 a0 = __half22float2(*(__half2*)&u0.x), b0 = __half22float2(*(__half2*)&u0.y);
            float2 a1 = __half22float2(*(__half2*)&u1.x), b1 = __half22float2(*(__half2*)&u1.y);
            float2 a2 = __half22float2(*(__half2*)&u2.x), b2 = __half22float2(*(__half2*)&u2.y);
            float2 a3 = __half22float2(*(__half2*)&u3.x), b3 = __half22float2(*(__half2*)&u3.y);
            ax += e0 * a0.x + e1 * a1.x + e2 * a2.x + e3 * a3.x;
            ay += e0 * a0.y + e1 * a1.y + e2 * a2.y + e3 * a3.y;
            az += e0 * b0.x + e1 * b1.x + e2 * b2.x + e3 * b3.x;
            aw += e0 * b0.y + e1 * b1.y + e2 * b2.y + e3 * b3.y;
            z += e0 + e1 + e2 + e3;
        }
        for (; j < cnt; j++) {
            int s = __shfl_sync(0xffffffffu, idx, j);
            float e = __shfl_sync(0xffffffffu, ef, j);
            uint2 u = hrow[s * 32 + lane];
            float2 f0 = __half22float2(*(__half2*)&u.x);
            float2 f1 = __half22float2(*(__half2*)&u.y);
            ax += e * f0.x;
            ay += e * f0.y;
            az += e * f1.x;
            aw += e * f1.y;
            z += e;
        }
    }
    float inv = 1.f / z;
    float4 b4 = *(const float4*)&bias[lane * 4];
    float c0 = ax * inv + b4.x;
    float c1 = ay * inv + b4.y;
    float c2 = az * inv + b4.z;
    float c3 = aw * inv + b4.w;
    if (MODE == 1) {
        c0 = fmaxf(c0, 0.f); c1 = fmaxf(c1, 0.f);
        c2 = fmaxf(c2, 0.f); c3 = fmaxf(c3, 0.f);
    }
    float tot = c0 + c1 + c2 + c3;
#pragma unroll
    for (int o = 16; o > 0; o >>= 1) tot += __shfl_xor_sync(0xffffffffu, tot, o);
    float mu = tot * (1.f / DH);
    float d0 = c0 - mu, d1 = c1 - mu, d2 = c2 - mu, d3 = c3 - mu;
    float ssq = d0 * d0 + d1 * d1 + d2 * d2 + d3 * d3;
#pragma unroll
    for (int o = 16; o > 0; o >>= 1) ssq += __shfl_xor_sync(0xffffffffu, ssq, o);
    float var = ssq * (1.f / DH);
    float sc = rsqrtf(var + EPSF);
    float4 g4 = *(const float4*)&lng[lane * 4];
    float4 bb = *(const float4*)&lnb[lane * 4];
    float o0 = d0 * sc * g4.x + bb.x;
    float o1 = d1 * sc * g4.y + bb.y;
    float o2 = d2 * sc * g4.z + bb.z;
    float o3 = d3 * sc * g4.w + bb.w;
    if (MODE == 2) {
        o0 = fmaxf(o0, 0.f); o1 = fmaxf(o1, 0.f);
        o2 = fmaxf(o2, 0.f); o3 = fmaxf(o3, 0.f);
    }
    *(float4*)&g_x2[w * DH + lane * 4] = make_float4(o0, o1, o2, o3);
}

// ---------------- fused bounds + pool + fc ----------------
__global__ void __launch_bounds__(512) k_poolfc(const void* batch,
                                                const float* __restrict__ fcW,
                                                const float* __restrict__ fcb) {
    __shared__ float part[4][DH];
    __shared__ float pr[DH];
    __shared__ int sbound[2];
    int g = blockIdx.x;
    int t = threadIdx.x;
    if (t < 2) {
        int is64 = g_is64;
        int target = g + t;
        int lo = 0, hi = NN;
        while (lo < hi) {
            int m = (lo + hi) >> 1;
            if (idx_at(batch, m, is64) < target) lo = m + 1;
            else hi = m;
        }
        sbound[t] = lo;
    }
    __syncthreads();
    int s = sbound[0], e = sbound[1];
    int c = t & 127;
    int q = t >> 7;
    int cnt = e - s;
    int chunk = (cnt + 3) >> 2;
    int rs = s + q * chunk;
    int re = min(rs + chunk, e);
    float sum = 0.f;
    for (int r = rs; r < re; r++) sum += g_x2[r * DH + c];
    part[q][c] = sum;
    __syncthreads();
    if (q == 0) {
        float tot2 = part[0][c] + part[1][c] + part[2][c] + part[3][c];
        pr[c] = tot2 / (float)max(cnt, 1);
    }
    __syncthreads();
    if (t < 128) {
        float acc = fcb[t];
#pragma unroll 4
        for (int k = 0; k < DH; k++) acc += pr[k] * fcW[k * DH + t];
        g_logits[g * DH + t] = acc;
    }
}

__global__ void k_bn(const float* __restrict__ bng, const float* __restrict__ bnb,
                     float* __restrict__ out) {
    int o = threadIdx.x;
    float mu = 0.f;
    for (int g = 0; g < GG; g++) mu += g_logits[g * DH + o];
    mu *= (1.f / GG);
    float var = 0.f;
    for (int g = 0; g < GG; g++) {
        float d = g_logits[g * DH + o] - mu;
        var += d * d;
    }
    var *= (1.f / GG);
    float sc = rsqrtf(var + EPSF);
    float gg = bng[o], bb = bnb[o];
    for (int g = 0; g < GG; g++)
        out[g * DH + o] = (g_logits[g * DH + o] - mu) * sc * gg + bb;
}

// ---------------- launch ----------------
extern "C" void kernel_launch(void* const* d_in, const int* in_sizes, int n_in,
                              void* d_out, int out_size) {
    const float* x    = (const float*)d_in[0];
    const void*  ei   = d_in[1];
    const void*  bat  = d_in[2];
    const float* W1   = (const float*)d_in[3];
    const float* as1  = (const float*)d_in[4];
    const float* ad1  = (const float*)d_in[5];
    const float* b1   = (const float*)d_in[6];
    const float* W2   = (const float*)d_in[7];
    const float* as2  = (const float*)d_in[8];
    const float* ad2  = (const float*)d_in[9];
    const float* b2   = (const float*)d_in[10];
    const float* ln1g = (const float*)d_in[11];
    const float* ln1b = (const float*)d_in[12];
    const float* ln2g = (const float*)d_in[13];
    const float* ln2b = (const float*)d_in[14];
    const float* fcW  = (const float*)d_in[15];
    const float* fcb  = (const float*)d_in[16];
    const float* bng  = (const float*)d_in[17];
    const float* bnb  = (const float*)d_in[18];
    float* out = (float*)d_out;
    int E = in_sizes[1] / 2;

    cudaFuncSetAttribute(k_hmma, cudaFuncAttributeMaxDynamicSharedMemorySize, HMMA_SMEM);

    // hmma1 stays the 4th launch for profiling continuity
    k_zero<<<98, 512>>>();
    k_wprep<<<128, 256>>>(W1, W2);
    k_detect<<<1, 256>>>((const int*)ei);
    k_hmma<<<TILES, 256, HMMA_SMEM>>>(x, 0, as1, ad1);

    k_hist<<<1024, 256>>>(ei, E);
    k_scan_bsum<<<SCAN_NB, SCAN_B>>>();
    k_scan_top<<<1, 256>>>();
    k_scan_expand<<<SCAN_NB, SCAN_B>>>();
    k_scatter<<<1024, 256>>>(ei, E);

    k_agg<1><<<NN / 8, 256>>>(b1, ln1g, ln1b);

    k_hmma<<<TILES, 256, HMMA_SMEM>>>(nullptr, 1, as2, ad2);
    k_agg<2><<<NN / 8, 256>>>(b2, ln2g, ln2b);

    k_poolfc<<<GG, 512>>>(bat, fcW, fcb);
    k_bn<<<1, 128>>>(bng, bnb, out);
}